// round 12
// baseline (speedup 1.0000x reference)
#include <cuda_runtime.h>
#include <cuda_bf16.h>
#include <cstdint>
#include <math.h>

namespace {
constexpr int TT = 4096;   // tokens (B*S)
constexpr int DD = 1024;   // model dim
constexpr int EE = 8;      // experts
constexpr int FF = 4096;   // ffn dim
}

// ---------------- device scratch (no runtime allocation allowed) -----------
__device__ int g_expert_id[TT];
__device__ int g_counts[EE];
__device__ int g_offsets[EE];
__device__ int g_cursor[EE];
__device__ int g_perm[TT];
__device__ __nv_bfloat16 g_h_hi[(size_t)TT * FF];   // 32 MB
__device__ __nv_bfloat16 g_h_lo[(size_t)TT * FF];   // 32 MB

// ---------------- helpers ---------------------------------------------------
__device__ __forceinline__ uint32_t smem_u32(const void* p) {
    uint32_t a;
    asm("{ .reg .u64 t; cvta.to.shared.u64 t, %1; cvt.u32.u64 %0, t; }" : "=r"(a) : "l"(p));
    return a;
}
// fp32 -> bf16 (hi, lo) split, packed as bf16x2 pairs
__device__ __forceinline__ void split2(float a, float b, uint32_t& hi, uint32_t& lo) {
    __nv_bfloat16 ha = __float2bfloat16(a);
    __nv_bfloat16 hb = __float2bfloat16(b);
    __nv_bfloat16 la = __float2bfloat16(a - __bfloat162float(ha));
    __nv_bfloat16 lb = __float2bfloat16(b - __bfloat162float(hb));
    __nv_bfloat162 ph; ph.x = ha; ph.y = hb;
    __nv_bfloat162 pl; pl.x = la; pl.y = lb;
    hi = *reinterpret_cast<uint32_t*>(&ph);
    lo = *reinterpret_cast<uint32_t*>(&pl);
}
__device__ __forceinline__ float gelu_exact(float x) {
    return 0.5f * x * (1.0f + erff(x * 0.70710678118654752f));
}
__device__ __forceinline__ void sts128(uint32_t addr, uint32_t a, uint32_t b,
                                       uint32_t c, uint32_t d) {
    asm volatile("st.shared.v4.b32 [%0], {%1, %2, %3, %4};"
                 :: "r"(addr), "r"(a), "r"(b), "r"(c), "r"(d) : "memory");
}
#define LDSM4(r, addr)                                                           \
    asm volatile("ldmatrix.sync.aligned.m8n8.x4.shared.b16 {%0,%1,%2,%3}, [%4];" \
                 : "=r"((r)[0]), "=r"((r)[1]), "=r"((r)[2]), "=r"((r)[3])        \
                 : "r"(addr))
#define LDSM4T(r, addr)                                                          \
    asm volatile("ldmatrix.sync.aligned.m8n8.x4.trans.shared.b16 {%0,%1,%2,%3}, [%4];" \
                 : "=r"((r)[0]), "=r"((r)[1]), "=r"((r)[2]), "=r"((r)[3])        \
                 : "r"(addr))
#define MMA_BF16(d, a, b0, b1)                                                   \
    asm volatile("mma.sync.aligned.m16n8k16.row.col.f32.bf16.bf16.f32 "          \
                 "{%0,%1,%2,%3}, {%4,%5,%6,%7}, {%8,%9}, {%0,%1,%2,%3};"         \
                 : "+f"((d)[0]), "+f"((d)[1]), "+f"((d)[2]), "+f"((d)[3])        \
                 : "r"((a)[0]), "r"((a)[1]), "r"((a)[2]), "r"((a)[3]),           \
                   "r"(b0), "r"(b1))

// ---------------- bookkeeping (validated) ------------------------------------
__global__ void moe_router(const float* __restrict__ x, const float* __restrict__ gw) {
    __shared__ float sg[EE * DD];
    for (int i = threadIdx.x; i < EE * DD; i += blockDim.x) sg[i] = gw[i];
    __syncthreads();
    const int warp = threadIdx.x >> 5, lane = threadIdx.x & 31;
    const int token = blockIdx.x * 8 + warp;
    const float* xr = x + (size_t)token * DD;
    float acc[EE];
    #pragma unroll
    for (int e = 0; e < EE; e++) acc[e] = 0.f;
    for (int k = lane; k < DD; k += 32) {
        const float xv = xr[k];
        #pragma unroll
        for (int e = 0; e < EE; e++) acc[e] = fmaf(xv, sg[e * DD + k], acc[e]);
    }
    #pragma unroll
    for (int e = 0; e < EE; e++) {
        #pragma unroll
        for (int off = 16; off > 0; off >>= 1)
            acc[e] += __shfl_xor_sync(0xffffffffu, acc[e], off);
    }
    if (lane == 0) {
        int best = 0; float bv = acc[0];
        #pragma unroll
        for (int e = 1; e < EE; e++)
            if (acc[e] > bv) { bv = acc[e]; best = e; }   // first-max = jnp.argmax
        g_expert_id[token] = best;
    }
}

__global__ void moe_scan_scatter() {
    __shared__ int hist[EE];
    if (threadIdx.x < EE) hist[threadIdx.x] = 0;
    __syncthreads();
    for (int t = threadIdx.x; t < TT; t += blockDim.x)
        atomicAdd(&hist[g_expert_id[t]], 1);
    __syncthreads();
    if (threadIdx.x == 0) {
        int s = 0;
        for (int e = 0; e < EE; e++) {
            g_counts[e]  = hist[e];
            g_offsets[e] = s;
            g_cursor[e]  = s;
            s += hist[e];
        }
    }
    __syncthreads();
    for (int t = threadIdx.x; t < TT; t += blockDim.x) {
        const int e = g_expert_id[t];
        g_perm[atomicAdd(&g_cursor[e], 1)] = t;
    }
}

// ---------------- grouped GEMM: mma.sync bf16 hi/lo (3-pass fp32 emu) -------
// Mainloop/fragment maps identical to the validated R5/R10 kernel. Change:
// LDG/STS remap so each thread handles 8 contiguous k-values of ONE row ->
// 4x sts128 per thread (was 8x sts64), conflict-free by construction, and
// 32B-contiguous LDGs. (row,k)->smem address is unchanged, so ldmatrix and
// results are bit-identical.
//   thread -> A: row = (tid&7)+(tid>>4)*8, half = (tid>>3)&1 (k = half*8..+7)
//   thread -> B: krow = tid>>4, colgrp = tid&15 (8 cols)
template<int KDIM, int NDIM, int PHASE>
__global__ __launch_bounds__(256) void moe_gemm_mma(
    const float* __restrict__ Araw,     // PHASE1: x [TT][DD]
    const float* __restrict__ Wraw,     // [EE][KDIM][NDIM]
    float* __restrict__ Out)
{
    // layout: A(buf,split) = (buf*2+split)*6144, row stride 48  (128 rows)
    //         B(buf,split) = 24576 + (buf*2+split)*4352, row stride 272 (16 rows)
    __shared__ __align__(128) char sm[41984];
    const int e   = blockIdx.z;
    const int cnt = g_counts[e];
    const int m0  = blockIdx.x * 128;
    if (m0 >= cnt) return;
    const int off = g_offsets[e];
    const int n0  = blockIdx.y * 128;
    const uint32_t sb = smem_u32(sm);

    const int tid = threadIdx.x, lane = tid & 31, wid = tid >> 5;
    const int warpM = wid >> 2, warpN = wid & 3;

    // ---- fixed per-thread source pointers ----
    const int rowA = (tid & 7) + (tid >> 4) * 8;   // 0..127, each row by 2 threads
    const int half = (tid >> 3) & 1;               // k-half within 16-k stage
    bool aV = false;
    const float* aP1 = nullptr;
    const __nv_bfloat16 *aP2h = nullptr, *aP2l = nullptr;
    if (PHASE == 1) {
        aV = (m0 + rowA) < cnt;
        const size_t tok = aV ? (size_t)g_perm[off + m0 + rowA] : 0;
        aP1 = Araw + tok * KDIM + half * 8;
    } else {
        const int rc = (m0 + rowA) < cnt ? rowA : 0;
        const size_t rowoff = (size_t)(off + m0 + rc) * KDIM + half * 8;
        aP2h = g_h_hi + rowoff;
        aP2l = g_h_lo + rowoff;
    }
    const int krow = tid >> 4;          // 0..15
    const int cg   = tid & 15;          // 8-col group
    const float* bP = Wraw + (size_t)e * KDIM * NDIM + n0 + cg * 8;
    const uint32_t aDst = (uint32_t)rowA * 48 + (uint32_t)half * 16;
    const uint32_t bDst = (uint32_t)krow * 272 + (uint32_t)cg * 16;

    // ---- staging registers ----
    float4 aS0, aS1;  uint4 aSh, aSl;  float4 bS0, bS1;

    auto ldg_stage = [&](int s) {
        const int k0 = s * 16;
        if (PHASE == 1) {
            if (aV) {
                aS0 = *(const float4*)(aP1 + k0);
                aS1 = *(const float4*)(aP1 + k0 + 4);
            } else {
                aS0 = make_float4(0.f, 0.f, 0.f, 0.f);
                aS1 = aS0;
            }
        } else {
            aSh = *(const uint4*)(aP2h + k0);
            aSl = *(const uint4*)(aP2l + k0);
        }
        const float* bsrc = bP + (size_t)(k0 + krow) * NDIM;
        bS0 = *(const float4*)(bsrc);
        bS1 = *(const float4*)(bsrc + 4);
    };
    auto sts_stage = [&](int s) {
        const int buf = s & 1;
        const uint32_t ah = sb + (uint32_t)(buf * 2) * 6144;
        const uint32_t al = ah + 6144;
        if (PHASE == 1) {
            uint32_t h0, l0, h1, l1, h2, l2, h3, l3;
            split2(aS0.x, aS0.y, h0, l0);
            split2(aS0.z, aS0.w, h1, l1);
            split2(aS1.x, aS1.y, h2, l2);
            split2(aS1.z, aS1.w, h3, l3);
            sts128(ah + aDst, h0, h1, h2, h3);
            sts128(al + aDst, l0, l1, l2, l3);
        } else {
            sts128(ah + aDst, aSh.x, aSh.y, aSh.z, aSh.w);
            sts128(al + aDst, aSl.x, aSl.y, aSl.z, aSl.w);
        }
        const uint32_t bh = sb + 24576 + (uint32_t)(buf * 2) * 4352;
        const uint32_t bl = bh + 4352;
        uint32_t h0, l0, h1, l1, h2, l2, h3, l3;
        split2(bS0.x, bS0.y, h0, l0);
        split2(bS0.z, bS0.w, h1, l1);
        split2(bS1.x, bS1.y, h2, l2);
        split2(bS1.z, bS1.w, h3, l3);
        sts128(bh + bDst, h0, h1, h2, h3);
        sts128(bl + bDst, l0, l1, l2, l3);
    };

    float acc[4][4][4];
    #pragma unroll
    for (int a = 0; a < 4; ++a)
        #pragma unroll
        for (int b = 0; b < 4; ++b)
            #pragma unroll
            for (int c = 0; c < 4; ++c) acc[a][b][c] = 0.f;

    // ldmatrix per-thread offsets (unchanged)
    const uint32_t aFragOff =
        (uint32_t)(warpM * 64 + (lane & 15)) * 48 + (uint32_t)(lane >> 4) * 16;
    const uint32_t bFragOff =
        (uint32_t)(lane & 15) * 272 + (uint32_t)(warpN * 64) + (uint32_t)(lane >> 4) * 16;

    constexpr int NS = KDIM / 16;
    ldg_stage(0);
    sts_stage(0);
    __syncthreads();

    for (int s = 0; s < NS; ++s) {
        if (s + 1 < NS) ldg_stage(s + 1);

        const int buf = s & 1;
        const uint32_t aH = sb + (uint32_t)(buf * 2) * 6144 + aFragOff;
        const uint32_t aL = aH + 6144;
        const uint32_t bH = sb + 24576 + (uint32_t)(buf * 2) * 4352 + bFragOff;
        const uint32_t bL = bH + 4352;

        uint32_t ah[4][4], al[4][4], bh[2][4], bl[2][4];
        #pragma unroll
        for (int mf = 0; mf < 4; ++mf) {
            LDSM4(ah[mf], aH + (uint32_t)mf * 768);   // 16 rows * 48B
            LDSM4(al[mf], aL + (uint32_t)mf * 768);
        }
        #pragma unroll
        for (int nq = 0; nq < 2; ++nq) {
            LDSM4T(bh[nq], bH + (uint32_t)nq * 32);   // 16 n-cols * 2B
            LDSM4T(bl[nq], bL + (uint32_t)nq * 32);
        }
        #pragma unroll
        for (int mf = 0; mf < 4; ++mf)
            #pragma unroll
            for (int nf = 0; nf < 4; ++nf) {
                const int nq = nf >> 1, hh = nf & 1;
                MMA_BF16(acc[mf][nf], ah[mf], bh[nq][2 * hh], bh[nq][2 * hh + 1]);
            }
        #pragma unroll
        for (int mf = 0; mf < 4; ++mf)
            #pragma unroll
            for (int nf = 0; nf < 4; ++nf) {
                const int nq = nf >> 1, hh = nf & 1;
                MMA_BF16(acc[mf][nf], ah[mf], bl[nq][2 * hh], bl[nq][2 * hh + 1]);
            }
        #pragma unroll
        for (int mf = 0; mf < 4; ++mf)
            #pragma unroll
            for (int nf = 0; nf < 4; ++nf) {
                const int nq = nf >> 1, hh = nf & 1;
                MMA_BF16(acc[mf][nf], al[mf], bh[nq][2 * hh], bh[nq][2 * hh + 1]);
            }

        if (s + 1 < NS) {
            sts_stage(s + 1);
            __syncthreads();
        }
    }

    // ---- epilogue ----
    const int rBase = m0 + warpM * 64 + (lane >> 2);
    const int cBase = n0 + warpN * 32 + (lane & 3) * 2;
    #pragma unroll
    for (int mf = 0; mf < 4; ++mf) {
        #pragma unroll
        for (int rr = 0; rr < 2; ++rr) {
            const int gr = rBase + mf * 16 + rr * 8;
            if (gr >= cnt) continue;
            if (PHASE == 1) {
                const size_t rowoff = (size_t)(off + gr) * NDIM;
                #pragma unroll
                for (int nf = 0; nf < 4; ++nf) {
                    const float f0 = gelu_exact(acc[mf][nf][rr * 2 + 0]);
                    const float f1 = gelu_exact(acc[mf][nf][rr * 2 + 1]);
                    uint32_t h, l;
                    split2(f0, f1, h, l);
                    *reinterpret_cast<uint32_t*>(g_h_hi + rowoff + cBase + nf * 8) = h;
                    *reinterpret_cast<uint32_t*>(g_h_lo + rowoff + cBase + nf * 8) = l;
                }
            } else {
                const int tok = g_perm[off + gr];
                float* dst = Out + (size_t)tok * DD + cBase;
                #pragma unroll
                for (int nf = 0; nf < 4; ++nf)
                    *reinterpret_cast<float2*>(dst + nf * 8) =
                        make_float2(acc[mf][nf][rr * 2 + 0], acc[mf][nf][rr * 2 + 1]);
            }
        }
    }
}

// ---------------- launch ----------------------------------------------------
extern "C" void kernel_launch(void* const* d_in, const int* in_sizes, int n_in,
                              void* d_out, int out_size) {
    (void)in_sizes; (void)n_in; (void)out_size;
    const float* x  = (const float*)d_in[0];
    const float* gw = (const float*)d_in[1];
    const float* w1 = (const float*)d_in[2];   // [E][D][F]
    const float* w2 = (const float*)d_in[3];   // [E][F][D]
    float* out = (float*)d_out;

    moe_router<<<TT / 8, 256>>>(x, gw);                       // local 0
    moe_scan_scatter<<<1, 256>>>();                           // local 1
    // GEMM1: h = gelu(x_gathered @ w1[e]); K=D, N=F            local 2
    moe_gemm_mma<DD, FF, 1><<<dim3(32, FF / 128, EE), 256>>>(x, w1, nullptr);
    // GEMM2: out = h @ w2[e] scattered; K=F, N=D               local 3 (ncu -s 5)
    moe_gemm_mma<FF, DD, 2><<<dim3(32, DD / 128, EE), 256>>>(x, w2, out);
}

// round 13
// speedup vs baseline: 1.1033x; 1.1033x over previous
#include <cuda_runtime.h>
#include <cuda_bf16.h>
#include <cstdint>
#include <math.h>

namespace {
constexpr int TT = 4096;   // tokens (B*S)
constexpr int DD = 1024;   // model dim
constexpr int EE = 8;      // experts
constexpr int FF = 4096;   // ffn dim
}

// ---------------- device scratch (no runtime allocation allowed) -----------
__device__ int g_expert_id[TT];
__device__ int g_counts[EE];
__device__ int g_offsets[EE];
__device__ int g_cursor[EE];
__device__ int g_perm[TT];
__device__ __nv_bfloat16 g_h_hi[(size_t)TT * FF];   // 32 MB
__device__ __nv_bfloat16 g_h_lo[(size_t)TT * FF];   // 32 MB

// ---------------- helpers ---------------------------------------------------
__device__ __forceinline__ uint32_t smem_u32(const void* p) {
    uint32_t a;
    asm("{ .reg .u64 t; cvta.to.shared.u64 t, %1; cvt.u32.u64 %0, t; }" : "=r"(a) : "l"(p));
    return a;
}
// fp32 -> bf16 (hi, lo) split, packed as bf16x2 pairs
__device__ __forceinline__ void split2(float a, float b, uint32_t& hi, uint32_t& lo) {
    __nv_bfloat16 ha = __float2bfloat16(a);
    __nv_bfloat16 hb = __float2bfloat16(b);
    __nv_bfloat16 la = __float2bfloat16(a - __bfloat162float(ha));
    __nv_bfloat16 lb = __float2bfloat16(b - __bfloat162float(hb));
    __nv_bfloat162 ph; ph.x = ha; ph.y = hb;
    __nv_bfloat162 pl; pl.x = la; pl.y = lb;
    hi = *reinterpret_cast<uint32_t*>(&ph);
    lo = *reinterpret_cast<uint32_t*>(&pl);
}
__device__ __forceinline__ float gelu_exact(float x) {
    return 0.5f * x * (1.0f + erff(x * 0.70710678118654752f));
}
__device__ __forceinline__ void sts64(uint32_t addr, uint32_t a, uint32_t b) {
    asm volatile("st.shared.v2.b32 [%0], {%1, %2};" :: "r"(addr), "r"(a), "r"(b) : "memory");
}
__device__ __forceinline__ void sts128(uint32_t addr, uint4 v) {
    asm volatile("st.shared.v4.b32 [%0], {%1, %2, %3, %4};"
                 :: "r"(addr), "r"(v.x), "r"(v.y), "r"(v.z), "r"(v.w) : "memory");
}
#define LDSM4(r, addr)                                                           \
    asm volatile("ldmatrix.sync.aligned.m8n8.x4.shared.b16 {%0,%1,%2,%3}, [%4];" \
                 : "=r"((r)[0]), "=r"((r)[1]), "=r"((r)[2]), "=r"((r)[3])        \
                 : "r"(addr))
#define LDSM4T(r, addr)                                                          \
    asm volatile("ldmatrix.sync.aligned.m8n8.x4.trans.shared.b16 {%0,%1,%2,%3}, [%4];" \
                 : "=r"((r)[0]), "=r"((r)[1]), "=r"((r)[2]), "=r"((r)[3])        \
                 : "r"(addr))
#define MMA_BF16(d, a, b0, b1)                                                   \
    asm volatile("mma.sync.aligned.m16n8k16.row.col.f32.bf16.bf16.f32 "          \
                 "{%0,%1,%2,%3}, {%4,%5,%6,%7}, {%8,%9}, {%0,%1,%2,%3};"         \
                 : "+f"((d)[0]), "+f"((d)[1]), "+f"((d)[2]), "+f"((d)[3])        \
                 : "r"((a)[0]), "r"((a)[1]), "r"((a)[2]), "r"((a)[3]),           \
                   "r"(b0), "r"(b1))

// ---------------- bookkeeping ------------------------------------------------
// router: logits argmax only (no global atomics)
__global__ void moe_router(const float* __restrict__ x, const float* __restrict__ gw) {
    __shared__ float sg[EE * DD];
    for (int i = threadIdx.x; i < EE * DD; i += blockDim.x) sg[i] = gw[i];
    __syncthreads();
    const int warp = threadIdx.x >> 5, lane = threadIdx.x & 31;
    const int token = blockIdx.x * 8 + warp;
    const float* xr = x + (size_t)token * DD;
    float acc[EE];
    #pragma unroll
    for (int e = 0; e < EE; e++) acc[e] = 0.f;
    for (int k = lane; k < DD; k += 32) {
        const float xv = xr[k];
        #pragma unroll
        for (int e = 0; e < EE; e++) acc[e] = fmaf(xv, sg[e * DD + k], acc[e]);
    }
    #pragma unroll
    for (int e = 0; e < EE; e++) {
        #pragma unroll
        for (int off = 16; off > 0; off >>= 1)
            acc[e] += __shfl_xor_sync(0xffffffffu, acc[e], off);
    }
    if (lane == 0) {
        int best = 0; float bv = acc[0];
        #pragma unroll
        for (int e = 1; e < EE; e++)
            if (acc[e] > bv) { bv = acc[e]; best = e; }   // first-max = jnp.argmax
        g_expert_id[token] = best;
    }
}

// fused histogram + scan + scatter (single block)
__global__ void moe_scan_scatter() {
    __shared__ int hist[EE];
    if (threadIdx.x < EE) hist[threadIdx.x] = 0;
    __syncthreads();
    for (int t = threadIdx.x; t < TT; t += blockDim.x)
        atomicAdd(&hist[g_expert_id[t]], 1);
    __syncthreads();
    if (threadIdx.x == 0) {
        int s = 0;
        for (int e = 0; e < EE; e++) {
            g_counts[e]  = hist[e];
            g_offsets[e] = s;
            g_cursor[e]  = s;
            s += hist[e];
        }
    }
    __syncthreads();
    for (int t = threadIdx.x; t < TT; t += blockDim.x) {
        const int e = g_expert_id[t];
        g_perm[atomicAdd(&g_cursor[e], 1)] = t;
    }
}

// ---------------- grouped GEMM: byte-exact R5 (643us champion) mainloop -----
// CTA 128M x 128N, K-stage 16, static-SMEM double buffer, LDG->reg->STS,
// interleaved 3-MMA fp32 emulation (hh, hl, lh per accumulator).
template<int KDIM, int NDIM, int PHASE>
__global__ __launch_bounds__(256) void moe_gemm_mma(
    const float* __restrict__ Araw,     // PHASE1: x [TT][DD]
    const float* __restrict__ Wraw,     // [EE][KDIM][NDIM]
    float* __restrict__ Out)
{
    // layout: A(buf,split) = (buf*2+split)*6144, row stride 48  (128 rows)
    //         B(buf,split) = 24576 + (buf*2+split)*4352, row stride 272 (16 rows)
    __shared__ __align__(128) char sm[41984];
    const int e   = blockIdx.z;
    const int cnt = g_counts[e];
    const int m0  = blockIdx.x * 128;
    if (m0 >= cnt) return;
    const int off = g_offsets[e];
    const int n0  = blockIdx.y * 128;
    const uint32_t sb = smem_u32(sm);

    const int tid = threadIdx.x, lane = tid & 31, wid = tid >> 5;
    const int warpM = wid >> 2, warpN = wid & 3;

    // ---- fixed per-thread source pointers ----
    const int rowA0 = tid >> 2;
    const int k4    = (tid & 3) * 4;
    const float* aP1[2];
    bool aV[2];
    const __nv_bfloat16 *aP2h = nullptr, *aP2l = nullptr;
    if (PHASE == 1) {
        #pragma unroll
        for (int i = 0; i < 2; ++i) {
            const int r = rowA0 + i * 64;
            aV[i] = (m0 + r) < cnt;
            const size_t tok = aV[i] ? (size_t)g_perm[off + m0 + r] : 0;
            aP1[i] = Araw + tok * KDIM + k4;
        }
    } else {
        const int r  = tid >> 1;
        const int rc = (m0 + r) < cnt ? r : 0;
        const size_t rowoff = (size_t)(off + m0 + rc) * KDIM + (tid & 1) * 8;
        aP2h = g_h_hi + rowoff;
        aP2l = g_h_lo + rowoff;
    }
    const int krow = tid >> 5;
    const int c4   = (tid & 31) * 4;
    const float* bP = Wraw + (size_t)e * KDIM * NDIM + n0 + c4;

    // ---- staging registers ----
    float4 aS[2];  uint4 aSh, aSl;  float4 bS[2];

    auto ldg_stage = [&](int s) {
        const int k0 = s * 16;
        if (PHASE == 1) {
            #pragma unroll
            for (int i = 0; i < 2; ++i)
                aS[i] = aV[i] ? *(const float4*)(aP1[i] + k0)
                              : make_float4(0.f, 0.f, 0.f, 0.f);
        } else {
            aSh = *(const uint4*)(aP2h + k0);
            aSl = *(const uint4*)(aP2l + k0);
        }
        #pragma unroll
        for (int i = 0; i < 2; ++i)
            bS[i] = *(const float4*)(bP + (size_t)(k0 + krow + i * 8) * NDIM);
    };
    auto sts_stage = [&](int s) {
        const int buf = s & 1;
        const uint32_t ah = sb + (uint32_t)(buf * 2) * 6144;
        const uint32_t al = ah + 6144;
        if (PHASE == 1) {
            #pragma unroll
            for (int i = 0; i < 2; ++i) {
                uint32_t h0, l0, h1, l1;
                split2(aS[i].x, aS[i].y, h0, l0);
                split2(aS[i].z, aS[i].w, h1, l1);
                const uint32_t o = (uint32_t)(rowA0 + i * 64) * 48 + (uint32_t)k4 * 2;
                sts64(ah + o, h0, h1);
                sts64(al + o, l0, l1);
            }
        } else {
            const uint32_t o = (uint32_t)(tid >> 1) * 48 + (uint32_t)(tid & 1) * 16;
            sts128(ah + o, aSh);
            sts128(al + o, aSl);
        }
        const uint32_t bh = sb + 24576 + (uint32_t)(buf * 2) * 4352;
        const uint32_t bl = bh + 4352;
        #pragma unroll
        for (int i = 0; i < 2; ++i) {
            uint32_t h0, l0, h1, l1;
            split2(bS[i].x, bS[i].y, h0, l0);
            split2(bS[i].z, bS[i].w, h1, l1);
            const uint32_t o = (uint32_t)(krow + i * 8) * 272 + (uint32_t)c4 * 2;
            sts64(bh + o, h0, h1);
            sts64(bl + o, l0, l1);
        }
    };

    float acc[4][4][4];
    #pragma unroll
    for (int a = 0; a < 4; ++a)
        #pragma unroll
        for (int b = 0; b < 4; ++b)
            #pragma unroll
            for (int c = 0; c < 4; ++c) acc[a][b][c] = 0.f;

    // ldmatrix per-thread offsets
    const uint32_t aFragOff =
        (uint32_t)(warpM * 64 + (lane & 15)) * 48 + (uint32_t)(lane >> 4) * 16;
    const uint32_t bFragOff =
        (uint32_t)(lane & 15) * 272 + (uint32_t)(warpN * 64) + (uint32_t)(lane >> 4) * 16;

    constexpr int NS = KDIM / 16;
    ldg_stage(0);
    sts_stage(0);
    __syncthreads();

    for (int s = 0; s < NS; ++s) {
        if (s + 1 < NS) ldg_stage(s + 1);

        const int buf = s & 1;
        const uint32_t aH = sb + (uint32_t)(buf * 2) * 6144 + aFragOff;
        const uint32_t aL = aH + 6144;
        const uint32_t bH = sb + 24576 + (uint32_t)(buf * 2) * 4352 + bFragOff;
        const uint32_t bL = bH + 4352;

        uint32_t ah[4][4], al[4][4], bh[2][4], bl[2][4];
        #pragma unroll
        for (int mf = 0; mf < 4; ++mf) {
            LDSM4(ah[mf], aH + (uint32_t)mf * 768);   // 16 rows * 48B
            LDSM4(al[mf], aL + (uint32_t)mf * 768);
        }
        #pragma unroll
        for (int nq = 0; nq < 2; ++nq) {
            LDSM4T(bh[nq], bH + (uint32_t)nq * 32);   // 16 n-cols * 2B
            LDSM4T(bl[nq], bL + (uint32_t)nq * 32);
        }
        #pragma unroll
        for (int mf = 0; mf < 4; ++mf)
            #pragma unroll
            for (int nf = 0; nf < 4; ++nf) {
                const int nq = nf >> 1, hh = nf & 1;
                MMA_BF16(acc[mf][nf], ah[mf], bh[nq][2 * hh], bh[nq][2 * hh + 1]);
                MMA_BF16(acc[mf][nf], ah[mf], bl[nq][2 * hh], bl[nq][2 * hh + 1]);
                MMA_BF16(acc[mf][nf], al[mf], bh[nq][2 * hh], bh[nq][2 * hh + 1]);
            }

        if (s + 1 < NS) {
            sts_stage(s + 1);
            __syncthreads();
        }
    }

    // ---- epilogue ----
    const int rBase = m0 + warpM * 64 + (lane >> 2);
    const int cBase = n0 + warpN * 32 + (lane & 3) * 2;
    #pragma unroll
    for (int mf = 0; mf < 4; ++mf) {
        #pragma unroll
        for (int rr = 0; rr < 2; ++rr) {
            const int gr = rBase + mf * 16 + rr * 8;
            if (gr >= cnt) continue;
            if (PHASE == 1) {
                const size_t rowoff = (size_t)(off + gr) * NDIM;
                #pragma unroll
                for (int nf = 0; nf < 4; ++nf) {
                    const float f0 = gelu_exact(acc[mf][nf][rr * 2 + 0]);
                    const float f1 = gelu_exact(acc[mf][nf][rr * 2 + 1]);
                    uint32_t h, l;
                    split2(f0, f1, h, l);
                    *reinterpret_cast<uint32_t*>(g_h_hi + rowoff + cBase + nf * 8) = h;
                    *reinterpret_cast<uint32_t*>(g_h_lo + rowoff + cBase + nf * 8) = l;
                }
            } else {
                const int tok = g_perm[off + gr];
                float* dst = Out + (size_t)tok * DD + cBase;
                #pragma unroll
                for (int nf = 0; nf < 4; ++nf)
                    *reinterpret_cast<float2*>(dst + nf * 8) =
                        make_float2(acc[mf][nf][rr * 2 + 0], acc[mf][nf][rr * 2 + 1]);
            }
        }
    }
}

// ---------------- launch ----------------------------------------------------
extern "C" void kernel_launch(void* const* d_in, const int* in_sizes, int n_in,
                              void* d_out, int out_size) {
    (void)in_sizes; (void)n_in; (void)out_size;
    const float* x  = (const float*)d_in[0];
    const float* gw = (const float*)d_in[1];
    const float* w1 = (const float*)d_in[2];   // [E][D][F]
    const float* w2 = (const float*)d_in[3];   // [E][F][D]
    float* out = (float*)d_out;

    moe_router<<<TT / 8, 256>>>(x, gw);                       // local 0
    moe_scan_scatter<<<1, 256>>>();                           // local 1
    // GEMM1: h = gelu(x_gathered @ w1[e]); K=D, N=F            local 2
    moe_gemm_mma<DD, FF, 1><<<dim3(32, FF / 128, EE), 256>>>(x, w1, nullptr);
    // GEMM2: out = h @ w2[e] scattered; K=F, N=D               local 3 (ncu -s 5)
    moe_gemm_mma<FF, DD, 2><<<dim3(32, DD / 128, EE), 256>>>(x, w2, out);
}